// round 10
// baseline (speedup 1.0000x reference)
#include <cuda_runtime.h>
#include <cstdint>

#define BATCH 512
#define TLEN  8192
#define DTC   1e-3f
#define NWARP 8
#define NTHR  (NWARP * 32)     // 256
#define LS    4                // steps per lane
#define TILE  (NTHR * LS)      // 1024
#define NTILE (TLEN / TILE)    // 8

// self = self ∘ prev (prev applied first)
__device__ __forceinline__ void compose(float& M00, float& M01, float& M10, float& M11,
                                        float& v0, float& v1,
                                        float pM00, float pM01, float pM10, float pM11,
                                        float pv0, float pv1) {
    float n00 = M00 * pM00 + M01 * pM10;
    float n01 = M00 * pM01 + M01 * pM11;
    float n10 = M10 * pM00 + M11 * pM10;
    float n11 = M10 * pM01 + M11 * pM11;
    float nv0 = M00 * pv0 + M01 * pv1 + v0;
    float nv1 = M10 * pv0 + M11 * pv1 + v1;
    M00 = n00; M01 = n01; M10 = n10; M11 = n11; v0 = nv0; v1 = nv1;
}

// T = I + dt*A - q*(dt*C);  b = q*d   (dta, dtc are pre-scaled by dt)
__device__ __forceinline__ void step_transform(float4 q, float dx, float dy_,
                                               float dta00, float dta01, float dta10, float dta11,
                                               float dtc00, float dtc01, float dtc10, float dtc11,
                                               float& T00, float& T01, float& T10, float& T11,
                                               float& b0, float& b1) {
    T00 = 1.0f + dta00 - (q.x * dtc00 + q.y * dtc10);
    T01 =        dta01 - (q.x * dtc01 + q.y * dtc11);
    T10 =        dta10 - (q.z * dtc00 + q.w * dtc10);
    T11 = 1.0f + dta11 - (q.z * dtc01 + q.w * dtc11);
    b0  = q.x * dx + q.y * dy_;
    b1  = q.z * dx + q.w * dy_;
}

// ---------------- Fused direct-load kernel, LS=4 ----------------
__global__ __launch_bounds__(NTHR, 4)
void kFused(const float4* __restrict__ xic, const float4* __restrict__ dyv4,
            const float* __restrict__ Ac, const float* __restrict__ Cm,
            float4* __restrict__ out4) {
    __shared__ float wc[NWARP][6];   // warp composites
    __shared__ float xs[NWARP][2];   // state at start of each warp's segment
    __shared__ float carry[2];       // state carried across tiles

    const int tid  = threadIdx.x;
    const int lane = tid & 31;
    const int w    = tid >> 5;
    const int b    = blockIdx.x;

    const float dtc00 = DTC * __ldg(Cm + 0), dtc01 = DTC * __ldg(Cm + 1);
    const float dtc10 = DTC * __ldg(Cm + 2), dtc11 = DTC * __ldg(Cm + 3);
    const float dta00 = DTC * __ldg(Ac + 0), dta01 = DTC * __ldg(Ac + 1);
    const float dta10 = DTC * __ldg(Ac + 2), dta11 = DTC * __ldg(Ac + 3);

    if (tid == 0) { carry[0] = 1.0f; carry[1] = 0.0f; }

    const size_t rowbase = (size_t)b * TLEN;
    const int s0 = w * (32 * LS) + lane * LS;     // this thread's first step within a tile

    const float4* xp = xic  + rowbase + s0;
    const float4* dp = dyv4 + ((rowbase + s0) >> 1);
    float4*       op = out4 + ((rowbase + s0) >> 1);

    // prologue: load tile 0 (4 q, 2 d-pairs)
    float4 q0 = __ldg(xp),     q1 = __ldg(xp + 1);
    float4 q2 = __ldg(xp + 2), q3 = __ldg(xp + 3);
    float4 d01 = __ldg(dp), d23 = __ldg(dp + 1);

    for (int tile = 0; tile < NTILE; tile++) {
        // --- 4 per-step transforms (kept for replay); frees q/d registers ---
        float T00, T01, T10, T11, Tb0, Tb1;
        float U00, U01, U10, U11, Ub0, Ub1;
        float V00, V01, V10, V11, Vb0, Vb1;
        float W00, W01, W10, W11, Wb0, Wb1;
        step_transform(q0, d01.x, d01.y, dta00, dta01, dta10, dta11, dtc00, dtc01, dtc10, dtc11,
                       T00, T01, T10, T11, Tb0, Tb1);
        step_transform(q1, d01.z, d01.w, dta00, dta01, dta10, dta11, dtc00, dtc01, dtc10, dtc11,
                       U00, U01, U10, U11, Ub0, Ub1);
        step_transform(q2, d23.x, d23.y, dta00, dta01, dta10, dta11, dtc00, dtc01, dtc10, dtc11,
                       V00, V01, V10, V11, Vb0, Vb1);
        step_transform(q3, d23.z, d23.w, dta00, dta01, dta10, dta11, dtc00, dtc01, dtc10, dtc11,
                       W00, W01, W10, W11, Wb0, Wb1);

        // --- prefetch next tile into now-dead q/d registers ---
        if (tile + 1 < NTILE) {
            const float4* xn = xp + (tile + 1) * TILE;
            const float4* dn = dp + (tile + 1) * (TILE / 2);
            q0 = __ldg(xn);     q1 = __ldg(xn + 1);
            q2 = __ldg(xn + 2); q3 = __ldg(xn + 3);
            d01 = __ldg(dn); d23 = __ldg(dn + 1);
        }

        // --- lane composite = W ∘ V ∘ U ∘ T (tree: (U∘T), (W∘V), then compose) ---
        float M00 = U00, M01 = U01, M10 = U10, M11 = U11, v0 = Ub0, v1 = Ub1;
        compose(M00, M01, M10, M11, v0, v1, T00, T01, T10, T11, Tb0, Tb1);     // U∘T
        float N00 = W00, N01 = W01, N10 = W10, N11 = W11, n0 = Wb0, n1 = Wb1;
        compose(N00, N01, N10, N11, n0, n1, V00, V01, V10, V11, Vb0, Vb1);     // W∘V
        compose(N00, N01, N10, N11, n0, n1, M00, M01, M10, M11, v0, v1);       // (W∘V)∘(U∘T)
        M00 = N00; M01 = N01; M10 = N10; M11 = N11; v0 = n0; v1 = n1;

        // --- warp inclusive scan ---
        #pragma unroll
        for (int d = 1; d < 32; d <<= 1) {
            float pM00 = __shfl_up_sync(0xffffffffu, M00, d);
            float pM01 = __shfl_up_sync(0xffffffffu, M01, d);
            float pM10 = __shfl_up_sync(0xffffffffu, M10, d);
            float pM11 = __shfl_up_sync(0xffffffffu, M11, d);
            float pv0  = __shfl_up_sync(0xffffffffu, v0,  d);
            float pv1  = __shfl_up_sync(0xffffffffu, v1,  d);
            if (lane >= d) compose(M00, M01, M10, M11, v0, v1, pM00, pM01, pM10, pM11, pv0, pv1);
        }

        if (lane == 31) {
            wc[w][0] = M00; wc[w][1] = M01; wc[w][2] = M10;
            wc[w][3] = M11; wc[w][4] = v0;  wc[w][5] = v1;
        }
        __syncthreads();   // sync A: wc ready

        // --- warp 0, lanes 0-7: scan warp composites, derive per-warp start states ---
        if (w == 0 && lane < NWARP) {
            float cx0 = carry[0], cx1 = carry[1];
            float S00 = wc[lane][0], S01 = wc[lane][1], S10 = wc[lane][2];
            float S11 = wc[lane][3], Sv0 = wc[lane][4], Sv1 = wc[lane][5];
            #pragma unroll
            for (int d = 1; d < NWARP; d <<= 1) {
                float pM00 = __shfl_up_sync(0xffu, S00, d);
                float pM01 = __shfl_up_sync(0xffu, S01, d);
                float pM10 = __shfl_up_sync(0xffu, S10, d);
                float pM11 = __shfl_up_sync(0xffu, S11, d);
                float pv0  = __shfl_up_sync(0xffu, Sv0, d);
                float pv1  = __shfl_up_sync(0xffu, Sv1, d);
                if (lane >= d) compose(S00, S01, S10, S11, Sv0, Sv1, pM00, pM01, pM10, pM11, pv0, pv1);
            }
            float eM00 = __shfl_up_sync(0xffu, S00, 1);
            float eM01 = __shfl_up_sync(0xffu, S01, 1);
            float eM10 = __shfl_up_sync(0xffu, S10, 1);
            float eM11 = __shfl_up_sync(0xffu, S11, 1);
            float ev0  = __shfl_up_sync(0xffu, Sv0, 1);
            float ev1  = __shfl_up_sync(0xffu, Sv1, 1);
            if (lane == 0) { eM00 = 1.f; eM01 = 0.f; eM10 = 0.f; eM11 = 1.f; ev0 = 0.f; ev1 = 0.f; }

            xs[lane][0] = eM00 * cx0 + eM01 * cx1 + ev0;
            xs[lane][1] = eM10 * cx0 + eM11 * cx1 + ev1;
            if (lane == NWARP - 1) {
                carry[0] = S00 * cx0 + S01 * cx1 + Sv0;
                carry[1] = S10 * cx0 + S11 * cx1 + Sv1;
            }
        }
        __syncthreads();   // sync B: xs/carry ready

        // --- exclusive lane prefix, apply to warp start state ---
        float pM00 = __shfl_up_sync(0xffffffffu, M00, 1);
        float pM01 = __shfl_up_sync(0xffffffffu, M01, 1);
        float pM10 = __shfl_up_sync(0xffffffffu, M10, 1);
        float pM11 = __shfl_up_sync(0xffffffffu, M11, 1);
        float pv0  = __shfl_up_sync(0xffffffffu, v0,  1);
        float pv1  = __shfl_up_sync(0xffffffffu, v1,  1);
        if (lane == 0) { pM00 = 1.f; pM01 = 0.f; pM10 = 0.f; pM11 = 1.f; pv0 = 0.f; pv1 = 0.f; }

        float xw0 = xs[w][0], xw1 = xs[w][1];
        float x0 = pM00 * xw0 + pM01 * xw1 + pv0;
        float x1 = pM10 * xw0 + pM11 * xw1 + pv1;

        // --- replay 4 steps from register transforms; two coalesced float4 stores ---
        float4 oA, oB;
        oA.x = dtc00 * x0 + dtc01 * x1;
        oA.y = dtc10 * x0 + dtc11 * x1;
        { float nx0 = T00 * x0 + T01 * x1 + Tb0, nx1 = T10 * x0 + T11 * x1 + Tb1; x0 = nx0; x1 = nx1; }
        oA.z = dtc00 * x0 + dtc01 * x1;
        oA.w = dtc10 * x0 + dtc11 * x1;
        { float nx0 = U00 * x0 + U01 * x1 + Ub0, nx1 = U10 * x0 + U11 * x1 + Ub1; x0 = nx0; x1 = nx1; }
        oB.x = dtc00 * x0 + dtc01 * x1;
        oB.y = dtc10 * x0 + dtc11 * x1;
        { float nx0 = V00 * x0 + V01 * x1 + Vb0, nx1 = V10 * x0 + V11 * x1 + Vb1; x0 = nx0; x1 = nx1; }
        oB.z = dtc00 * x0 + dtc01 * x1;
        oB.w = dtc10 * x0 + dtc11 * x1;

        float4* o = op + tile * (TILE / 2);
        o[0] = oA;
        o[1] = oB;
    }
}

extern "C" void kernel_launch(void* const* d_in, const int* in_sizes, int n_in,
                              void* d_out, int out_size) {
    const float4* xic  = (const float4*)d_in[0];  // [B,T,2,2] f32
    const float4* dyv4 = (const float4*)d_in[1];  // [B,T,2]   f32, float4 = 2 steps
    const float*  Ac   = (const float*)d_in[2];   // [2,2]
    const float*  Cm   = (const float*)d_in[3];   // [2,2]
    float4* out4 = (float4*)d_out;                // [B,T,2] viewed as float4 pairs

    kFused<<<BATCH, NTHR>>>(xic, dyv4, Ac, Cm, out4);
}

// round 11
// speedup vs baseline: 1.3571x; 1.3571x over previous
#include <cuda_runtime.h>
#include <cstdint>

#define BATCH 512
#define TLEN  8192
#define DTC   1e-3f
#define NWARP 8
#define NTHR  (NWARP * 32)     // 256
#define LS    2                // steps per lane
#define TILE  (NTHR * LS)      // 512
#define NTILE (TLEN / TILE)    // 16
#define SEGW  8                // scan segment width (lanes)
#define NSEG  (NTHR / SEGW)    // 32 segments per block

// self = self ∘ prev (prev applied first)
__device__ __forceinline__ void compose(float& M00, float& M01, float& M10, float& M11,
                                        float& v0, float& v1,
                                        float pM00, float pM01, float pM10, float pM11,
                                        float pv0, float pv1) {
    float n00 = M00 * pM00 + M01 * pM10;
    float n01 = M00 * pM01 + M01 * pM11;
    float n10 = M10 * pM00 + M11 * pM10;
    float n11 = M10 * pM01 + M11 * pM11;
    float nv0 = M00 * pv0 + M01 * pv1 + v0;
    float nv1 = M10 * pv0 + M11 * pv1 + v1;
    M00 = n00; M01 = n01; M10 = n10; M11 = n11; v0 = nv0; v1 = nv1;
}

// T = I + dtA - q*(dtC);  b = q*d
__device__ __forceinline__ void step_transform(float4 q, float dx, float dy_,
                                               float dta00, float dta01, float dta10, float dta11,
                                               float dtc00, float dtc01, float dtc10, float dtc11,
                                               float& T00, float& T01, float& T10, float& T11,
                                               float& b0, float& b1) {
    T00 = 1.0f + dta00 - (q.x * dtc00 + q.y * dtc10);
    T01 =        dta01 - (q.x * dtc01 + q.y * dtc11);
    T10 =        dta10 - (q.z * dtc00 + q.w * dtc10);
    T11 = 1.0f + dta11 - (q.z * dtc01 + q.w * dtc11);
    b0  = q.x * dx + q.y * dy_;
    b1  = q.z * dx + q.w * dy_;
}

// ---------------- Fused direct-load kernel, 8-wide segmented scan ----------------
__global__ __launch_bounds__(NTHR, 4)
void kFused(const float4* __restrict__ xic, const float4* __restrict__ dyv4,
            const float* __restrict__ Ac, const float* __restrict__ Cm,
            float4* __restrict__ out4) {
    __shared__ float wc[NSEG][6];    // segment composites (32 segments)
    __shared__ float xs[NSEG][2];    // state at start of each segment
    __shared__ float carry[2];       // state carried across tiles

    const int tid  = threadIdx.x;
    const int lane = tid & 31;
    const int w    = tid >> 5;
    const int seg  = tid >> 3;       // 8-lane segment index (0..31)
    const int sl   = lane & 7;       // lane within segment
    const int b    = blockIdx.x;

    const float dtc00 = DTC * __ldg(Cm + 0), dtc01 = DTC * __ldg(Cm + 1);
    const float dtc10 = DTC * __ldg(Cm + 2), dtc11 = DTC * __ldg(Cm + 3);
    const float dta00 = DTC * __ldg(Ac + 0), dta01 = DTC * __ldg(Ac + 1);
    const float dta10 = DTC * __ldg(Ac + 2), dta11 = DTC * __ldg(Ac + 3);

    if (tid == 0) { carry[0] = 1.0f; carry[1] = 0.0f; }

    const size_t rowbase = (size_t)b * TLEN;
    const int s0 = tid * LS;                      // this thread's first step within a tile

    const float4* xp = xic  + rowbase + s0;
    const float4* dp = dyv4 + ((rowbase + s0) >> 1);
    float4*       op = out4 + ((rowbase + s0) >> 1);

    // prologue: load tile 0
    float4 q0  = __ldcs(xp);
    float4 q1  = __ldcs(xp + 1);
    float4 d01 = __ldcs(dp);                      // (d0.x, d0.y, d1.x, d1.y)

    for (int tile = 0; tile < NTILE; tile++) {
        // --- transforms for this tile (consume q0,q1,d01) ---
        float T00, T01, T10, T11, B00, B01;       // step 0 (kept for replay)
        float U00, U01, U10, U11, B10, B11;       // step 1
        step_transform(q0, d01.x, d01.y, dta00, dta01, dta10, dta11,
                       dtc00, dtc01, dtc10, dtc11, T00, T01, T10, T11, B00, B01);
        step_transform(q1, d01.z, d01.w, dta00, dta01, dta10, dta11,
                       dtc00, dtc01, dtc10, dtc11, U00, U01, U10, U11, B10, B11);

        // --- prefetch next tile into the now-dead registers ---
        if (tile + 1 < NTILE) {
            const float4* xn = xp + (tile + 1) * TILE;
            const float4* dn = dp + (tile + 1) * (TILE / 2);
            q0  = __ldcs(xn);
            q1  = __ldcs(xn + 1);
            d01 = __ldcs(dn);
        }

        // lane composite = U ∘ T
        float M00 = U00 * T00 + U01 * T10;
        float M01 = U00 * T01 + U01 * T11;
        float M10 = U10 * T00 + U11 * T10;
        float M11 = U10 * T01 + U11 * T11;
        float v0  = U00 * B00 + U01 * B01 + B10;
        float v1  = U10 * B00 + U11 * B01 + B11;

        // --- 8-wide segmented inclusive scan (3 rounds) ---
        #pragma unroll
        for (int d = 1; d < SEGW; d <<= 1) {
            float pM00 = __shfl_up_sync(0xffffffffu, M00, d, SEGW);
            float pM01 = __shfl_up_sync(0xffffffffu, M01, d, SEGW);
            float pM10 = __shfl_up_sync(0xffffffffu, M10, d, SEGW);
            float pM11 = __shfl_up_sync(0xffffffffu, M11, d, SEGW);
            float pv0  = __shfl_up_sync(0xffffffffu, v0,  d, SEGW);
            float pv1  = __shfl_up_sync(0xffffffffu, v1,  d, SEGW);
            if (sl >= d) compose(M00, M01, M10, M11, v0, v1, pM00, pM01, pM10, pM11, pv0, pv1);
        }

        if (sl == SEGW - 1) {
            wc[seg][0] = M00; wc[seg][1] = M01; wc[seg][2] = M10;
            wc[seg][3] = M11; wc[seg][4] = v0;  wc[seg][5] = v1;
        }
        __syncthreads();   // sync A: wc ready

        // --- warp 0: scan the 32 segment composites, derive per-segment start states ---
        if (w == 0) {
            float cx0 = carry[0], cx1 = carry[1];
            float S00 = wc[lane][0], S01 = wc[lane][1], S10 = wc[lane][2];
            float S11 = wc[lane][3], Sv0 = wc[lane][4], Sv1 = wc[lane][5];
            #pragma unroll
            for (int d = 1; d < 32; d <<= 1) {
                float pM00 = __shfl_up_sync(0xffffffffu, S00, d);
                float pM01 = __shfl_up_sync(0xffffffffu, S01, d);
                float pM10 = __shfl_up_sync(0xffffffffu, S10, d);
                float pM11 = __shfl_up_sync(0xffffffffu, S11, d);
                float pv0  = __shfl_up_sync(0xffffffffu, Sv0, d);
                float pv1  = __shfl_up_sync(0xffffffffu, Sv1, d);
                if (lane >= d) compose(S00, S01, S10, S11, Sv0, Sv1, pM00, pM01, pM10, pM11, pv0, pv1);
            }
            // segment-end states, shifted down one to get segment-start states
            float xe0 = S00 * cx0 + S01 * cx1 + Sv0;
            float xe1 = S10 * cx0 + S11 * cx1 + Sv1;
            float xb0 = __shfl_up_sync(0xffffffffu, xe0, 1);
            float xb1 = __shfl_up_sync(0xffffffffu, xe1, 1);
            if (lane == 0) { xb0 = cx0; xb1 = cx1; }
            xs[lane][0] = xb0;
            xs[lane][1] = xb1;
            if (lane == 31) { carry[0] = xe0; carry[1] = xe1; }
        }
        __syncthreads();   // sync B: xs/carry ready

        // --- segment entry state; lane end state; lane start via 2-shfl ---
        float xg0 = xs[seg][0], xg1 = xs[seg][1];
        float xe0 = M00 * xg0 + M01 * xg1 + v0;     // state at END of this lane's 2 steps
        float xe1 = M10 * xg0 + M11 * xg1 + v1;
        float x0 = __shfl_up_sync(0xffffffffu, xe0, 1, SEGW);
        float x1 = __shfl_up_sync(0xffffffffu, xe1, 1, SEGW);
        if (sl == 0) { x0 = xg0; x1 = xg1; }        // lane start state

        // --- replay 2 steps from register transforms; one coalesced float4 store ---
        float4 o;
        o.x = dtc00 * x0 + dtc01 * x1;
        o.y = dtc10 * x0 + dtc11 * x1;
        {
            float nx0 = T00 * x0 + T01 * x1 + B00;
            float nx1 = T10 * x0 + T11 * x1 + B01;
            x0 = nx0; x1 = nx1;
        }
        o.z = dtc00 * x0 + dtc01 * x1;
        o.w = dtc10 * x0 + dtc11 * x1;

        __stcs(op + tile * (TILE / 2), o);
    }
}

extern "C" void kernel_launch(void* const* d_in, const int* in_sizes, int n_in,
                              void* d_out, int out_size) {
    const float4* xic  = (const float4*)d_in[0];  // [B,T,2,2] f32
    const float4* dyv4 = (const float4*)d_in[1];  // [B,T,2]   f32, float4 = 2 steps
    const float*  Ac   = (const float*)d_in[2];   // [2,2]
    const float*  Cm   = (const float*)d_in[3];   // [2,2]
    float4* out4 = (float4*)d_out;                // [B,T,2] viewed as float4 pairs

    kFused<<<BATCH, NTHR>>>(xic, dyv4, Ac, Cm, out4);
}